// round 6
// baseline (speedup 1.0000x reference)
#include <cuda_runtime.h>
#include <cstddef>

// Problem constants (fixed by the reference):
//   B_PAIRS=2048 pairs, each pair = 44 ligand nodes + 300 protein nodes (stride 344)
//   Only the ligand segment sums (even segments) feed the MLP.
//   MLP: 128 ->256 relu -> 128 relu -> 64 relu -> 1
#define B_PAIRS 2048
#define LIG     44
#define STRIDE  344
#define F_IN    128
#define N0      256
#define N1      128
#define N2      64
#define RTILE   4          // pairs per MLP block -> grid 512
#define THREADS 512        // MLP block size
#define ATHREADS 256       // segsum block size

typedef unsigned long long u64;

// 1 MB scratch for the per-pair feature sums.
__device__ float g_xs[B_PAIRS * F_IN];

// ---------------- packed fp32x2 helpers (sm_103a FFMA2) --------------------
#define PACK_F32X2(d, lo, hi) \
    asm("mov.b64 %0, {%1, %2};" : "=l"(d) : "f"(lo), "f"(hi))
#define UNPACK_F32X2(lo, hi, v) \
    asm("mov.b64 {%0, %1}, %2;" : "=f"(lo), "=f"(hi) : "l"(v))
#define FMA_F32X2(d, a, b, c) \
    asm("fma.rn.f32x2 %0, %1, %2, %3;" : "=l"(d) : "l"(a), "l"(b), "l"(c))
#define ADD_F32X2(d, a, b) \
    asm("add.rn.f32x2 %0, %1, %2;" : "=l"(d) : "l"(a), "l"(b))

// ============================================================================
// Kernel A: ligand segment sum. One block per pair (L2-resident hot set).
// ============================================================================
__global__ void __launch_bounds__(ATHREADS)
seg_sum_kernel(const float* __restrict__ features)
{
    __shared__ float4 part[8][32];
    const int tid  = threadIdx.x;
    const int pair = blockIdx.x;
    const int c4   = tid & 31;
    const int g    = tid >> 5;

    const float4* src = reinterpret_cast<const float4*>(features)
                      + (size_t)pair * STRIDE * (F_IN / 4) + c4;
    float4 acc = make_float4(0.f, 0.f, 0.f, 0.f);
#pragma unroll
    for (int r = g; r < LIG; r += 8) {
        float4 v = __ldcs(src + (size_t)r * (F_IN / 4));
        acc.x += v.x; acc.y += v.y; acc.z += v.z; acc.w += v.w;
    }
    part[g][c4] = acc;
    __syncthreads();

    if (tid < 32) {
        float4 s = part[0][tid];
#pragma unroll
        for (int gg = 1; gg < 8; ++gg) {
            float4 v = part[gg][tid];
            s.x += v.x; s.y += v.y; s.z += v.z; s.w += v.w;
        }
        reinterpret_cast<float4*>(g_xs)[pair * (F_IN / 4) + tid] = s;
    }
}

// ============================================================================
// Kernel B: 4-layer MLP, 4 rows per block, 512 threads, grid 512.
// Every layer: thread job = 1 column-pair x 4 rows over a k-slice.
// Dup-activation SMEM ((x,x) u64) -> inner loop: 1 LDG.64 + 2 LDS.128
// (broadcast) + 4 FFMA2 per 8 MACs, zero packing, dense weight lines.
// Partials reduced via a remapped all-thread pass through a stride-5 buffer.
// ============================================================================
__global__ void __launch_bounds__(THREADS, 3)
mlp_kernel(const float* __restrict__ W0, const float* __restrict__ b0,
           const float* __restrict__ W1, const float* __restrict__ b1,
           const float* __restrict__ W2, const float* __restrict__ b2,
           const float* __restrict__ Wout, const float* __restrict__ bout,
           float* __restrict__ out)
{
    __shared__ __align__(16) u64  xsD[F_IN][RTILE];   // 4 KB
    __shared__ __align__(16) u64  h0D[N0][RTILE];     // 8 KB
    __shared__ __align__(16) u64  h1D[N1][RTILE];     // 4 KB
    __shared__ __align__(16) float h2T[N2][RTILE];    // 1 KB
    __shared__ u64 pbuf[512 * 5];                     // 20 KB (stride 5 anti-bank)

    const int tid = threadIdx.x;
    const int p0  = blockIdx.x * RTILE;

    // Load 4 summed rows, duplicate-pack into SMEM.
    if (tid < 128) {
        const int pp = tid & 3;
        const int c4 = tid >> 2;                 // 0..31
        float4 v = reinterpret_cast<const float4*>(g_xs)
                       [(size_t)(p0 + pp) * (F_IN / 4) + c4];
        u64 d0, d1, d2, d3;
        PACK_F32X2(d0, v.x, v.x); PACK_F32X2(d1, v.y, v.y);
        PACK_F32X2(d2, v.z, v.z); PACK_F32X2(d3, v.w, v.w);
        xsD[c4 * 4 + 0][pp] = d0;
        xsD[c4 * 4 + 1][pp] = d1;
        xsD[c4 * 4 + 2][pp] = d2;
        xsD[c4 * 4 + 3][pp] = d3;
    }
    __syncthreads();

    // ======== Layer 0: [4,128]@[128,256]+b relu | 128 cp x 4 kq x 32 ========
    {
        const int cg = tid & 127;                // colpair: cols 2cg, 2cg+1
        const int kq = tid >> 7;                 // 0..3, 32 k each
        u64 acc0 = 0, acc1 = 0, acc2 = 0, acc3 = 0;
        const float* Wp = W0 + (size_t)(kq * 32) * N0 + 2 * cg;
#pragma unroll 8
        for (int kk = 0; kk < 32; ++kk) {
            u64 w = *reinterpret_cast<const u64*>(Wp + (size_t)kk * N0);
            const u64* ap = &xsD[kq * 32 + kk][0];
            ulonglong2 a01 = *reinterpret_cast<const ulonglong2*>(ap);
            ulonglong2 a23 = *reinterpret_cast<const ulonglong2*>(ap + 2);
            FMA_F32X2(acc0, a01.x, w, acc0);
            FMA_F32X2(acc1, a01.y, w, acc1);
            FMA_F32X2(acc2, a23.x, w, acc2);
            FMA_F32X2(acc3, a23.y, w, acc3);
        }
        u64* dst = &pbuf[(kq * 128 + cg) * 5];
        dst[0] = acc0; dst[1] = acc1; dst[2] = acc2; dst[3] = acc3;
    }
    __syncthreads();
    {
        const int cg = tid & 127;
        const int r  = tid >> 7;                 // 0..3
        u64 s = pbuf[cg * 5 + r];
#pragma unroll
        for (int q = 1; q < 4; ++q) {
            u64 t2 = pbuf[(q * 128 + cg) * 5 + r];
            ADD_F32X2(s, s, t2);
        }
        u64 bb = *reinterpret_cast<const u64*>(b0 + 2 * cg);
        ADD_F32X2(s, s, bb);
        float v0, v1; UNPACK_F32X2(v0, v1, s);
        v0 = fmaxf(v0, 0.f); v1 = fmaxf(v1, 0.f);
        u64 d0, d1; PACK_F32X2(d0, v0, v0); PACK_F32X2(d1, v1, v1);
        h0D[2 * cg    ][r] = d0;
        h0D[2 * cg + 1][r] = d1;
    }
    __syncthreads();

    // ======== Layer 1: [4,256]@[256,128]+b relu | 64 cp x 8 kq x 32 =========
    {
        const int cg = tid & 63;
        const int kq = tid >> 6;                 // 0..7, 32 k each
        u64 acc0 = 0, acc1 = 0, acc2 = 0, acc3 = 0;
        const float* Wp = W1 + (size_t)(kq * 32) * N1 + 2 * cg;
#pragma unroll 8
        for (int kk = 0; kk < 32; ++kk) {
            u64 w = *reinterpret_cast<const u64*>(Wp + (size_t)kk * N1);
            const u64* ap = &h0D[kq * 32 + kk][0];
            ulonglong2 a01 = *reinterpret_cast<const ulonglong2*>(ap);
            ulonglong2 a23 = *reinterpret_cast<const ulonglong2*>(ap + 2);
            FMA_F32X2(acc0, a01.x, w, acc0);
            FMA_F32X2(acc1, a01.y, w, acc1);
            FMA_F32X2(acc2, a23.x, w, acc2);
            FMA_F32X2(acc3, a23.y, w, acc3);
        }
        u64* dst = &pbuf[(kq * 64 + cg) * 5];
        dst[0] = acc0; dst[1] = acc1; dst[2] = acc2; dst[3] = acc3;
    }
    __syncthreads();
    {
        const int cg = tid & 63;
        const int r  = tid >> 6;                 // 0..7, active r<4
        if (r < 4) {
            u64 s = pbuf[cg * 5 + r];
#pragma unroll
            for (int q = 1; q < 8; ++q) {
                u64 t2 = pbuf[(q * 64 + cg) * 5 + r];
                ADD_F32X2(s, s, t2);
            }
            u64 bb = *reinterpret_cast<const u64*>(b1 + 2 * cg);
            ADD_F32X2(s, s, bb);
            float v0, v1; UNPACK_F32X2(v0, v1, s);
            v0 = fmaxf(v0, 0.f); v1 = fmaxf(v1, 0.f);
            u64 d0, d1; PACK_F32X2(d0, v0, v0); PACK_F32X2(d1, v1, v1);
            h1D[2 * cg    ][r] = d0;
            h1D[2 * cg + 1][r] = d1;
        }
    }
    __syncthreads();

    // ======== Layer 2: [4,128]@[128,64]+b relu | 32 cp x 16 kq x 8 ==========
    {
        const int cg = tid & 31;
        const int kq = tid >> 5;                 // 0..15, 8 k each
        u64 acc0 = 0, acc1 = 0, acc2 = 0, acc3 = 0;
        const float* Wp = W2 + (size_t)(kq * 8) * N2 + 2 * cg;
#pragma unroll
        for (int kk = 0; kk < 8; ++kk) {
            u64 w = *reinterpret_cast<const u64*>(Wp + (size_t)kk * N2);
            const u64* ap = &h1D[kq * 8 + kk][0];
            ulonglong2 a01 = *reinterpret_cast<const ulonglong2*>(ap);
            ulonglong2 a23 = *reinterpret_cast<const ulonglong2*>(ap + 2);
            FMA_F32X2(acc0, a01.x, w, acc0);
            FMA_F32X2(acc1, a01.y, w, acc1);
            FMA_F32X2(acc2, a23.x, w, acc2);
            FMA_F32X2(acc3, a23.y, w, acc3);
        }
        u64* dst = &pbuf[(kq * 32 + cg) * 5];
        dst[0] = acc0; dst[1] = acc1; dst[2] = acc2; dst[3] = acc3;
    }
    __syncthreads();
    {
        const int cg = tid & 31;
        const int r  = tid >> 5;                 // 0..15, active r<4
        if (r < 4) {
            u64 s = pbuf[cg * 5 + r];
#pragma unroll
            for (int q = 1; q < 16; ++q) {
                u64 t2 = pbuf[(q * 32 + cg) * 5 + r];
                ADD_F32X2(s, s, t2);
            }
            u64 bb = *reinterpret_cast<const u64*>(b2 + 2 * cg);
            ADD_F32X2(s, s, bb);
            float v0, v1; UNPACK_F32X2(v0, v1, s);
            h2T[2 * cg    ][r] = fmaxf(v0, 0.f);
            h2T[2 * cg + 1][r] = fmaxf(v1, 0.f);
        }
    }
    __syncthreads();

    // ======== Output: [4,64]@[64,1]+b ========================================
    {
        const int warp = tid >> 5;
        const int lane = tid & 31;
        if (warp < RTILE) {
            float s = h2T[2 * lane][warp]     * Wout[2 * lane]
                    + h2T[2 * lane + 1][warp] * Wout[2 * lane + 1];
#pragma unroll
            for (int o = 16; o > 0; o >>= 1)
                s += __shfl_down_sync(0xffffffffu, s, o);
            if (lane == 0)
                out[p0 + warp] = s + bout[0];
        }
    }
}

// d_in order (metadata): [0] batch_num_nodes (unused), [1] features,
// [2] W0, [3] b0, [4] W1, [5] b1, [6] W2, [7] b2, [8] Wout, [9] bout.
extern "C" void kernel_launch(void* const* d_in, const int* in_sizes, int n_in,
                              void* d_out, int out_size)
{
    const float* features = (const float*)d_in[1];
    const float* W0   = (const float*)d_in[2];
    const float* b0   = (const float*)d_in[3];
    const float* W1   = (const float*)d_in[4];
    const float* b1   = (const float*)d_in[5];
    const float* W2   = (const float*)d_in[6];
    const float* b2   = (const float*)d_in[7];
    const float* Wout = (const float*)d_in[8];
    const float* bout = (const float*)d_in[9];
    float* out = (float*)d_out;

    seg_sum_kernel<<<B_PAIRS, ATHREADS>>>(features);
    mlp_kernel<<<B_PAIRS / RTILE, THREADS>>>(W0, b0, W1, b1, W2, b2,
                                             Wout, bout, out);
}

// round 7
// speedup vs baseline: 1.2538x; 1.2538x over previous
#include <cuda_runtime.h>
#include <cstddef>

// Problem constants (fixed by the reference):
//   B_PAIRS=2048 pairs, each pair = 44 ligand nodes + 300 protein nodes (stride 344)
//   Only the ligand segment sums (even segments) feed the MLP.
//   MLP: 128 ->256 relu -> 128 relu -> 64 relu -> 1
#define B_PAIRS 2048
#define LIG     44
#define STRIDE  344
#define F_IN    128
#define N0      256
#define N1      128
#define N2      64
#define RTILE   4          // pairs per MLP block -> grid 512
#define THREADS 256

typedef unsigned long long u64;

// 1 MB scratch for the per-pair feature sums.
__device__ float g_xs[B_PAIRS * F_IN];

// ---------------- packed fp32x2 helpers (sm_103a FFMA2) --------------------
#define PACK_F32X2(d, lo, hi) \
    asm("mov.b64 %0, {%1, %2};" : "=l"(d) : "f"(lo), "f"(hi))
#define UNPACK_F32X2(lo, hi, v) \
    asm("mov.b64 {%0, %1}, %2;" : "=f"(lo), "=f"(hi) : "l"(v))
#define FMA_F32X2(d, a, b, c) \
    asm("fma.rn.f32x2 %0, %1, %2, %3;" : "=l"(d) : "l"(a), "l"(b), "l"(c))
#define ADD_F32X2(d, a, b) \
    asm("add.rn.f32x2 %0, %1, %2;" : "=l"(d) : "l"(a), "l"(b))

// ============================================================================
// Kernel A: ligand segment sum. One block per pair; DRAM-bound (46 MB once).
// ============================================================================
__global__ void __launch_bounds__(THREADS)
seg_sum_kernel(const float* __restrict__ features)
{
    __shared__ float4 part[8][32];
    const int tid  = threadIdx.x;
    const int pair = blockIdx.x;
    const int c4   = tid & 31;
    const int g    = tid >> 5;

    const float4* src = reinterpret_cast<const float4*>(features)
                      + (size_t)pair * STRIDE * (F_IN / 4) + c4;
    float4 acc = make_float4(0.f, 0.f, 0.f, 0.f);
#pragma unroll
    for (int r = g; r < LIG; r += 8) {
        float4 v = __ldcs(src + (size_t)r * (F_IN / 4));
        acc.x += v.x; acc.y += v.y; acc.z += v.z; acc.w += v.w;
    }
    part[g][c4] = acc;
    __syncthreads();

    if (tid < 32) {
        float4 s = part[0][tid];
#pragma unroll
        for (int gg = 1; gg < 8; ++gg) {
            float4 v = part[gg][tid];
            s.x += v.x; s.y += v.y; s.z += v.z; s.w += v.w;
        }
        reinterpret_cast<float4*>(g_xs)[pair * (F_IN / 4) + tid] = s;
    }
}

// ============================================================================
// Kernel B: 4-layer MLP, 4 rows per block, 256 threads, grid 512.
// Inner iteration: 1 LDG.128 (4 weight cols, packed pairs) + 2 LDS.128
// (4 dup-rows) + 8 FFMA2 = 11 slots / 32 MACs. Zero packing in loops.
// ============================================================================
__global__ void __launch_bounds__(THREADS)
mlp_kernel(const float* __restrict__ W0, const float* __restrict__ b0,
           const float* __restrict__ W1, const float* __restrict__ b1,
           const float* __restrict__ W2, const float* __restrict__ b2,
           const float* __restrict__ Wout, const float* __restrict__ bout,
           float* __restrict__ out)
{
    __shared__ __align__(16) u64  xsD[F_IN][RTILE];   // 4 KB dup activations
    __shared__ __align__(16) u64  h0D[N0][RTILE];     // 8 KB
    __shared__ __align__(16) u64  h1D[N1][RTILE];     // 4 KB
    __shared__ __align__(16) float h2T[N2][RTILE];    // 1 KB
    __shared__ __align__(16) u64  pbuf[7 * 32 * 8];   // 14 KB partials

    const int tid = threadIdx.x;
    const int p0  = blockIdx.x * RTILE;

    // Load 4 summed rows, duplicate-pack into SMEM.
    if (tid < 128) {
        const int pp = tid & 3;
        const int c4 = tid >> 2;                 // 0..31
        float4 v = reinterpret_cast<const float4*>(g_xs)
                       [(size_t)(p0 + pp) * (F_IN / 4) + c4];
        u64 d0, d1, d2, d3;
        PACK_F32X2(d0, v.x, v.x); PACK_F32X2(d1, v.y, v.y);
        PACK_F32X2(d2, v.z, v.z); PACK_F32X2(d3, v.w, v.w);
        xsD[c4 * 4 + 0][pp] = d0;
        xsD[c4 * 4 + 1][pp] = d1;
        xsD[c4 * 4 + 2][pp] = d2;
        xsD[c4 * 4 + 3][pp] = d3;
    }
    __syncthreads();

    // ======== Layer 0: [4,128]@[128,256]+b relu | 64 jobs(4col) x 4 kq ======
    {
        const int cg = tid & 63;                 // cols 4cg..4cg+3
        const int kq = tid >> 6;                 // 0..3, 32 k each
        u64 acc[8];                              // [colpair0/1][row0..3]
        if (kq == 0) {
            ulonglong2 bp = *reinterpret_cast<const ulonglong2*>(b0 + 4 * cg);
            acc[0] = bp.x; acc[1] = bp.x; acc[2] = bp.x; acc[3] = bp.x;
            acc[4] = bp.y; acc[5] = bp.y; acc[6] = bp.y; acc[7] = bp.y;
        } else {
#pragma unroll
            for (int i = 0; i < 8; ++i) acc[i] = 0ull;
        }
        const float* Wp = W0 + (size_t)(kq * 32) * N0 + 4 * cg;
#pragma unroll 8
        for (int kk = 0; kk < 32; ++kk) {
            ulonglong2 w = *reinterpret_cast<const ulonglong2*>(
                               Wp + (size_t)kk * N0);
            const u64* ap = &xsD[kq * 32 + kk][0];
            ulonglong2 a01 = *reinterpret_cast<const ulonglong2*>(ap);
            ulonglong2 a23 = *reinterpret_cast<const ulonglong2*>(ap + 2);
            FMA_F32X2(acc[0], a01.x, w.x, acc[0]);
            FMA_F32X2(acc[1], a01.y, w.x, acc[1]);
            FMA_F32X2(acc[2], a23.x, w.x, acc[2]);
            FMA_F32X2(acc[3], a23.y, w.x, acc[3]);
            FMA_F32X2(acc[4], a01.x, w.y, acc[4]);
            FMA_F32X2(acc[5], a01.y, w.y, acc[5]);
            FMA_F32X2(acc[6], a23.x, w.y, acc[6]);
            FMA_F32X2(acc[7], a23.y, w.y, acc[7]);
        }
        if (kq > 0) {
            u64* dst = &pbuf[((kq - 1) * 64 + cg) * 8];
#pragma unroll
            for (int i = 0; i < 8; i += 2)
                *reinterpret_cast<ulonglong2*>(dst + i) =
                    make_ulonglong2(acc[i], acc[i + 1]);
        }
        __syncthreads();
        if (kq == 0) {
#pragma unroll
            for (int t = 0; t < 3; ++t) {
                const u64* q = &pbuf[(t * 64 + cg) * 8];
#pragma unroll
                for (int i = 0; i < 8; i += 2) {
                    ulonglong2 qq = *reinterpret_cast<const ulonglong2*>(q + i);
                    ADD_F32X2(acc[i],     acc[i],     qq.x);
                    ADD_F32X2(acc[i + 1], acc[i + 1], qq.y);
                }
            }
#pragma unroll
            for (int cp = 0; cp < 2; ++cp)
#pragma unroll
                for (int r = 0; r < 4; ++r) {
                    float v0, v1; UNPACK_F32X2(v0, v1, acc[cp * 4 + r]);
                    v0 = fmaxf(v0, 0.f); v1 = fmaxf(v1, 0.f);
                    u64 d0, d1; PACK_F32X2(d0, v0, v0); PACK_F32X2(d1, v1, v1);
                    h0D[4 * cg + 2 * cp    ][r] = d0;
                    h0D[4 * cg + 2 * cp + 1][r] = d1;
                }
        }
    }
    __syncthreads();

    // ======== Layer 1: [4,256]@[256,128]+b relu | 32 jobs(4col) x 8 kq ======
    {
        const int cg = tid & 31;                 // cols 4cg..4cg+3
        const int kq = tid >> 5;                 // 0..7, 32 k each
        u64 acc[8];
        if (kq == 0) {
            ulonglong2 bp = *reinterpret_cast<const ulonglong2*>(b1 + 4 * cg);
            acc[0] = bp.x; acc[1] = bp.x; acc[2] = bp.x; acc[3] = bp.x;
            acc[4] = bp.y; acc[5] = bp.y; acc[6] = bp.y; acc[7] = bp.y;
        } else {
#pragma unroll
            for (int i = 0; i < 8; ++i) acc[i] = 0ull;
        }
        const float* Wp = W1 + (size_t)(kq * 32) * N1 + 4 * cg;
#pragma unroll 8
        for (int kk = 0; kk < 32; ++kk) {
            ulonglong2 w = *reinterpret_cast<const ulonglong2*>(
                               Wp + (size_t)kk * N1);
            const u64* ap = &h0D[kq * 32 + kk][0];
            ulonglong2 a01 = *reinterpret_cast<const ulonglong2*>(ap);
            ulonglong2 a23 = *reinterpret_cast<const ulonglong2*>(ap + 2);
            FMA_F32X2(acc[0], a01.x, w.x, acc[0]);
            FMA_F32X2(acc[1], a01.y, w.x, acc[1]);
            FMA_F32X2(acc[2], a23.x, w.x, acc[2]);
            FMA_F32X2(acc[3], a23.y, w.x, acc[3]);
            FMA_F32X2(acc[4], a01.x, w.y, acc[4]);
            FMA_F32X2(acc[5], a01.y, w.y, acc[5]);
            FMA_F32X2(acc[6], a23.x, w.y, acc[6]);
            FMA_F32X2(acc[7], a23.y, w.y, acc[7]);
        }
        if (kq > 0) {
            u64* dst = &pbuf[((kq - 1) * 32 + cg) * 8];
#pragma unroll
            for (int i = 0; i < 8; i += 2)
                *reinterpret_cast<ulonglong2*>(dst + i) =
                    make_ulonglong2(acc[i], acc[i + 1]);
        }
        __syncthreads();
        if (kq == 0) {
#pragma unroll
            for (int t = 0; t < 7; ++t) {
                const u64* q = &pbuf[(t * 32 + cg) * 8];
#pragma unroll
                for (int i = 0; i < 8; i += 2) {
                    ulonglong2 qq = *reinterpret_cast<const ulonglong2*>(q + i);
                    ADD_F32X2(acc[i],     acc[i],     qq.x);
                    ADD_F32X2(acc[i + 1], acc[i + 1], qq.y);
                }
            }
#pragma unroll
            for (int cp = 0; cp < 2; ++cp)
#pragma unroll
                for (int r = 0; r < 4; ++r) {
                    float v0, v1; UNPACK_F32X2(v0, v1, acc[cp * 4 + r]);
                    v0 = fmaxf(v0, 0.f); v1 = fmaxf(v1, 0.f);
                    u64 d0, d1; PACK_F32X2(d0, v0, v0); PACK_F32X2(d1, v1, v1);
                    h1D[4 * cg + 2 * cp    ][r] = d0;
                    h1D[4 * cg + 2 * cp + 1][r] = d1;
                }
        }
    }
    __syncthreads();

    // ======== Layer 2: [4,128]@[128,64]+b relu | 32 jobs(2col) x 8 kq =======
    {
        const int cg = tid & 31;                 // cols 2cg, 2cg+1
        const int kq = tid >> 5;                 // 0..7, 16 k each
        u64 acc[4];
        if (kq == 0) {
            u64 bp = *reinterpret_cast<const u64*>(b2 + 2 * cg);
            acc[0] = bp; acc[1] = bp; acc[2] = bp; acc[3] = bp;
        } else {
            acc[0] = acc[1] = acc[2] = acc[3] = 0ull;
        }
        const float* Wp = W2 + (size_t)(kq * 16) * N2 + 2 * cg;
#pragma unroll
        for (int kk = 0; kk < 16; ++kk) {
            u64 w = *reinterpret_cast<const u64*>(Wp + (size_t)kk * N2);
            const u64* ap = &h1D[kq * 16 + kk][0];
            ulonglong2 a01 = *reinterpret_cast<const ulonglong2*>(ap);
            ulonglong2 a23 = *reinterpret_cast<const ulonglong2*>(ap + 2);
            FMA_F32X2(acc[0], a01.x, w, acc[0]);
            FMA_F32X2(acc[1], a01.y, w, acc[1]);
            FMA_F32X2(acc[2], a23.x, w, acc[2]);
            FMA_F32X2(acc[3], a23.y, w, acc[3]);
        }
        if (kq > 0) {
            u64* dst = &pbuf[((kq - 1) * 32 + cg) * 4];
            *reinterpret_cast<ulonglong2*>(dst)     = make_ulonglong2(acc[0], acc[1]);
            *reinterpret_cast<ulonglong2*>(dst + 2) = make_ulonglong2(acc[2], acc[3]);
        }
        __syncthreads();
        if (kq == 0) {
#pragma unroll
            for (int t = 0; t < 7; ++t) {
                const u64* q = &pbuf[(t * 32 + cg) * 4];
                ulonglong2 q0 = *reinterpret_cast<const ulonglong2*>(q);
                ulonglong2 q1 = *reinterpret_cast<const ulonglong2*>(q + 2);
                ADD_F32X2(acc[0], acc[0], q0.x);
                ADD_F32X2(acc[1], acc[1], q0.y);
                ADD_F32X2(acc[2], acc[2], q1.x);
                ADD_F32X2(acc[3], acc[3], q1.y);
            }
#pragma unroll
            for (int r = 0; r < 4; ++r) {
                float v0, v1; UNPACK_F32X2(v0, v1, acc[r]);
                h2T[2 * cg    ][r] = fmaxf(v0, 0.f);
                h2T[2 * cg + 1][r] = fmaxf(v1, 0.f);
            }
        }
    }
    __syncthreads();

    // ======== Output: [4,64]@[64,1]+b ========================================
    {
        const int warp = tid >> 5;
        const int lane = tid & 31;
        if (warp < RTILE) {
            float s = h2T[2 * lane][warp]     * Wout[2 * lane]
                    + h2T[2 * lane + 1][warp] * Wout[2 * lane + 1];
#pragma unroll
            for (int o = 16; o > 0; o >>= 1)
                s += __shfl_down_sync(0xffffffffu, s, o);
            if (lane == 0)
                out[p0 + warp] = s + bout[0];
        }
    }
}

// d_in order (metadata): [0] batch_num_nodes (unused), [1] features,
// [2] W0, [3] b0, [4] W1, [5] b1, [6] W2, [7] b2, [8] Wout, [9] bout.
extern "C" void kernel_launch(void* const* d_in, const int* in_sizes, int n_in,
                              void* d_out, int out_size)
{
    const float* features = (const float*)d_in[1];
    const float* W0   = (const float*)d_in[2];
    const float* b0   = (const float*)d_in[3];
    const float* W1   = (const float*)d_in[4];
    const float* b1   = (const float*)d_in[5];
    const float* W2   = (const float*)d_in[6];
    const float* b2   = (const float*)d_in[7];
    const float* Wout = (const float*)d_in[8];
    const float* bout = (const float*)d_in[9];
    float* out = (float*)d_out;

    seg_sum_kernel<<<B_PAIRS, THREADS>>>(features);
    mlp_kernel<<<B_PAIRS / RTILE, THREADS>>>(W0, b0, W1, b1, W2, b2,
                                             Wout, bout, out);
}